// round 16
// baseline (speedup 1.0000x reference)
#include <cuda_runtime.h>
#include <cstdint>

#define NFX   32        // features f = 1..32 (f=0 is the exact identity flag slice)
#define BOND  64
#define CLU   8         // CTAs per cluster
#define ISL   8         // i-rows per CTA (one per warp)
#define NBC   16        // batches per cluster
#define NBP   8         // batch-pairs (u64 lanes)
#define TLEN  512
#define NTH   256
#define OUTD  32

typedef unsigned long long u64;

// ---- dynamic shared memory layout (bytes) ----
#define U_OFF    0
#define U_SZ     (ISL * NFX * NBP * 8)        // 16384
#define P_OFF    (U_OFF + U_SZ)
#define P_SZ     (512 * 9 * 8)                // 36864 (swizzled partials)
#define V_OFF    (P_OFF + P_SZ)
#define V_SZ     (BOND * 8)                   // 512   (this CTA's 8 rows x 8 bp)
#define MAIL_OFF (V_OFF + V_SZ)
#define MAIL_SZ  (2 * CLU * 64 * 8)           // 8192  (double-buffered scatter mailbox)
#define X_OFF    (MAIL_OFF + MAIL_SZ)
#define X_SZ     (2 * NFX * NBC * 4)          // 4096
#define SMEM_TOTAL (X_OFF + X_SZ)             // 66048

// ---- f32x2 packed math ----
__device__ __forceinline__ u64 pack2(float v) {
    u64 r; asm("mov.b64 %0, {%1, %1};" : "=l"(r) : "f"(v)); return r;
}
__device__ __forceinline__ void fma2(u64& d, u64 a, u64 b) {
    asm("fma.rn.f32x2 %0, %1, %2, %0;" : "+l"(d) : "l"(a), "l"(b));
}
__device__ __forceinline__ u64 mul2(u64 a, u64 b) {
    u64 r; asm("mul.rn.f32x2 %0, %1, %2;" : "=l"(r) : "l"(a), "l"(b)); return r;
}
__device__ __forceinline__ void add2(u64& d, u64 a) {
    asm("add.rn.f32x2 %0, %0, %1;" : "+l"(d) : "l"(a));
}

__device__ __forceinline__ void cp_async4(uint32_t smem_addr, const void* gptr) {
    asm volatile("cp.async.ca.shared.global [%0], [%1], 4;\n" :: "r"(smem_addr), "l"(gptr));
}
__device__ __forceinline__ void cp_async_commit() {
    asm volatile("cp.async.commit_group;\n" ::: "memory");
}
__device__ __forceinline__ void cp_async_wait0() {
    asm volatile("cp.async.wait_group 0;\n" ::: "memory");
}

__device__ __forceinline__ void st_cluster_u64(uint32_t laddr, int dst_rank, u64 v) {
    uint32_t raddr;
    asm volatile("mapa.shared::cluster.u32 %0, %1, %2;" : "=r"(raddr) : "r"(laddr), "r"(dst_rank));
    asm volatile("st.shared::cluster.b64 [%0], %1;" :: "r"(raddr), "l"(v) : "memory");
}
__device__ __forceinline__ void cluster_barrier() {
    asm volatile("barrier.cluster.arrive.aligned;" ::: "memory");
    asm volatile("barrier.cluster.wait.aligned;" ::: "memory");
}

__global__ __launch_bounds__(NTH, 1) __cluster_dims__(CLU, 1, 1)
void umps_w16_kernel(const float* __restrict__ x,      // (256, 512, 33)
                     const float* __restrict__ core,   // (64, 33, 64)
                     const float* __restrict__ alpha,  // (64)
                     const float* __restrict__ outc,   // (64, 32)
                     float*       __restrict__ out)    // (256, 32)
{
    extern __shared__ char smem[];
    u64*   sU    = (u64*)  (smem + U_OFF);    // [iL*256 + f'*8 + bp] (warp-private rows)
    u64*   sP    = (u64*)  (smem + P_OFF);    // [sc*9 + g] swizzled
    u64*   sVu   = (u64*)  (smem + V_OFF);    // [iL*8 + bp]  (this CTA's 8 rows)
    u64*   sMail = (u64*)  (smem + MAIL_OFF); // [(buf*8+src)*64 + pos]
    float* sX    = (float*)(smem + X_OFF);    // [buf][f'*16 + b]

    const int tid  = threadIdx.x;
    const int rank = blockIdx.x & 7;
    const int b0   = (blockIdx.x >> 3) * NBC;   // cluster batch base
    const int g    = tid >> 5;                  // warp = local i-row 0..7
    const int l    = tid & 31;                  // lane = j-pair index (j = 2l, 2l+1)
    const uint32_t sx_base   = (uint32_t)__cvta_generic_to_shared(sX);
    const uint32_t mail_base = (uint32_t)__cvta_generic_to_shared(sMail);

    // ---- core slice (f=1..32) -> REGISTERS: cR[f-1] = core[rank*8+g][f][2l..2l+1] ----
    float2 cR[NFX];
    {
        const float* cg = core + ((size_t)(rank * ISL + g) * 33) * BOND + 2 * l;
        #pragma unroll
        for (int f = 0; f < NFX; ++f) cR[f] = *(const float2*)(cg + (f + 1) * BOND);
    }

    // ---- init this CTA's V rows: V[iL][b] = alpha[rank*8 + iL] ----
    if (tid < 64) sVu[tid] = pack2(alpha[rank * ISL + (tid >> 3)]);

    // ---- preload X(t=0): 2 cp.async per thread (32 f x 16 b) ----
    #pragma unroll
    for (int h = 0; h < 2; ++h) {
        int p = tid + 256 * h;
        int f = p >> 4, bl = p & 15;
        cp_async4(sx_base + (uint32_t)(p * 4),
                  x + ((size_t)(b0 + bl) * TLEN + 0) * 33 + (f + 1));
    }
    cp_async_commit();

    for (int t = 0; t < TLEN; ++t) {
        cp_async_wait0();
        __syncthreads();                          // B0: X(t) landed, sVu(t) visible

        const int buf = t & 1;

        // ---- prefetch X(t+1) into buf^1 ----
        if (t + 1 < TLEN) {
            #pragma unroll
            for (int h = 0; h < 2; ++h) {
                int p = tid + 256 * h;
                int f = p >> 4, bl = p & 15;
                cp_async4(sx_base + (uint32_t)(((buf ^ 1) * NFX * NBC + p) * 4),
                          x + ((size_t)(b0 + bl) * TLEN + (t + 1)) * 33 + (f + 1));
            }
        }
        cp_async_commit();

        // ---- U-build (warp-private row g): U[g][f'][bp] = V[g][bp] * X[f'][bp] ----
        {
            const u64* sXu = (const u64*)(sX + buf * (NFX * NBC));
            u64 vv = sVu[g * 8 + (l & 7)];        // bp = (l+32k)&7 = l&7 for all k
            u64* Uw = sU + g * 256;
            #pragma unroll
            for (int k = 0; k < 8; ++k) {
                int r = l + 32 * k;               // r = f'*8 + bp
                Uw[r] = mul2(vv, sXu[r]);
            }
            __syncwarp();
        }

        // ---- GEMM over f=1..32: acc[jj*8+bp], j = 2l+jj, 16 batches ----
        u64 acc[16];
        #pragma unroll
        for (int q = 0; q < 16; ++q) acc[q] = 0ull;

        const ulonglong2* Ur = (const ulonglong2*)(sU + g * 256);
        #pragma unroll
        for (int f = 0; f < NFX; ++f) {
            ulonglong2 u01 = Ur[4 * f + 0];       // bp 0,1 (warp-broadcast)
            ulonglong2 u23 = Ur[4 * f + 1];       // bp 2,3
            ulonglong2 u45 = Ur[4 * f + 2];       // bp 4,5
            ulonglong2 u67 = Ur[4 * f + 3];       // bp 6,7
            u64 c0 = pack2(cR[f].x);
            u64 c1 = pack2(cR[f].y);
            fma2(acc[0],  u01.x, c0); fma2(acc[1],  u01.y, c0);
            fma2(acc[2],  u23.x, c0); fma2(acc[3],  u23.y, c0);
            fma2(acc[4],  u45.x, c0); fma2(acc[5],  u45.y, c0);
            fma2(acc[6],  u67.x, c0); fma2(acc[7],  u67.y, c0);
            fma2(acc[8],  u01.x, c1); fma2(acc[9],  u01.y, c1);
            fma2(acc[10], u23.x, c1); fma2(acc[11], u23.y, c1);
            fma2(acc[12], u45.x, c1); fma2(acc[13], u45.y, c1);
            fma2(acc[14], u67.x, c1); fma2(acc[15], u67.y, c1);
        }

        // ---- store partials, conflict-aware swizzle sc = q*32 + l ----
        #pragma unroll
        for (int q = 0; q < 16; ++q)
            sP[(q * 32 + l) * 9 + g] = acc[q];    // q = jj*8 + bp
        __syncthreads();                          // B2: partials visible

        // ---- reduce 8 i-rows for 2 columns; scatter to owner rank's mailbox ----
        #pragma unroll
        for (int h = 0; h < 2; ++h) {
            int sc = tid + 256 * h;
            u64 s = sP[sc * 9];
            #pragma unroll
            for (int gg = 1; gg < ISL; ++gg) add2(s, sP[sc * 9 + gg]);
            int q  = sc >> 5, l2 = sc & 31;
            int jj = q >> 3,  bp = q & 7;
            int j  = 2 * l2 + jj;
            int own = j >> 3;
            int pos = (j & 7) * 8 + bp;
            st_cluster_u64(mail_base + (uint32_t)(((buf * CLU + rank) * 64 + pos) * 8), own, s);
        }

        cluster_barrier();                        // all scatters visible

        // ---- owner-side: sum 8 rank-partials + V_old (exact f=0 identity) ----
        if (tid < 64) {
            const u64* mb = sMail + buf * (CLU * 64);
            u64 v = mb[tid];
            #pragma unroll
            for (int r = 1; r < CLU; ++r) add2(v, mb[r * 64 + tid]);
            add2(v, sVu[tid]);                    // V_new += V_old
            sVu[tid] = v;
        }
        // sVu visibility for next step via loop-top B0
    }

    // ---- gather final V rows to rank 0 (whole mail region is free now) ----
    if (tid < 64) {
        st_cluster_u64(mail_base + (uint32_t)((rank * 64 + tid) * 8), 0, sVu[tid]);
    }
    cluster_barrier();

    // ---- epilogue on rank 0: out[b][o] = sum_i V[i][b] * outc[i][o] ----
    if (rank == 0) {
        const float* Vf = (const float*)sMail;   // u64 slot (i>>3)*64 + (i&7)*8 + (b>>1)
        #pragma unroll
        for (int h = 0; h < 2; ++h) {
            int k = tid + 256 * h;
            int b = k >> 5, o = k & 31;
            float s = 0.f;
            #pragma unroll 8
            for (int i = 0; i < BOND; ++i) {
                float v = Vf[(((i >> 3) * 64 + (i & 7) * 8 + (b >> 1)) << 1) + (b & 1)];
                s = fmaf(v, __ldg(outc + i * OUTD + o), s);
            }
            out[(size_t)(b0 + b) * OUTD + o] = s;
        }
    }
}

extern "C" void kernel_launch(void* const* d_in, const int* in_sizes, int n_in,
                              void* d_out, int out_size) {
    const float* x     = (const float*)d_in[0];   // (256,512,33) fp32
    const float* core  = (const float*)d_in[1];   // (64,33,64)  fp32
    const float* alpha = (const float*)d_in[2];   // (64)        fp32
    const float* outc  = (const float*)d_in[3];   // (64,32)     fp32
    float* out = (float*)d_out;                   // (256,32)    fp32

    cudaFuncSetAttribute(umps_w16_kernel,
                         cudaFuncAttributeMaxDynamicSharedMemorySize, SMEM_TOTAL);
    // 16 clusters x 8 CTAs = 128 CTAs, 1 CTA/SM (no cross-cluster co-tenancy)
    umps_w16_kernel<<<128, NTH, SMEM_TOTAL>>>(x, core, alpha, outc, out);
}

// round 17
// speedup vs baseline: 2.1647x; 2.1647x over previous
#include <cuda_runtime.h>
#include <cstdint>

#define NFX   32        // features f = 1..32 (f=0 is the exact identity flag slice)
#define BOND  64
#define CLU   8         // CTAs per cluster
#define ISL   8         // i-rows per CTA (one per warp)
#define NBC   8         // batches per cluster
#define TLEN  512
#define NTH   256
#define OUTD  32

typedef unsigned long long u64;

// ---- f32x2 packed math ----
__device__ __forceinline__ u64 pack2(float v) {
    u64 r; asm("mov.b64 %0, {%1, %1};" : "=l"(r) : "f"(v)); return r;
}
__device__ __forceinline__ void fma2(u64& d, u64 a, u64 b) {
    asm("fma.rn.f32x2 %0, %1, %2, %0;" : "+l"(d) : "l"(a), "l"(b));
}
__device__ __forceinline__ u64 mul2(u64 a, u64 b) {
    u64 r; asm("mul.rn.f32x2 %0, %1, %2;" : "=l"(r) : "l"(a), "l"(b)); return r;
}
__device__ __forceinline__ void add2(u64& d, u64 a) {
    asm("add.rn.f32x2 %0, %0, %1;" : "+l"(d) : "l"(a));
}

__device__ __forceinline__ void cp_async4(uint32_t smem_addr, const void* gptr) {
    asm volatile("cp.async.ca.shared.global [%0], [%1], 4;\n" :: "r"(smem_addr), "l"(gptr));
}
__device__ __forceinline__ void cp_async_commit() {
    asm volatile("cp.async.commit_group;\n" ::: "memory");
}
__device__ __forceinline__ void cp_async_wait0() {
    asm volatile("cp.async.wait_group 0;\n" ::: "memory");
}

__device__ __forceinline__ void st_cluster_u64(uint32_t laddr, int dst_rank, u64 v) {
    uint32_t raddr;
    asm volatile("mapa.shared::cluster.u32 %0, %1, %2;" : "=r"(raddr) : "r"(laddr), "r"(dst_rank));
    asm volatile("st.shared::cluster.b64 [%0], %1;" :: "r"(raddr), "l"(v) : "memory");
}
__device__ __forceinline__ void mbar_arrive_remote(uint32_t laddr, int dst_rank) {
    uint32_t raddr;
    asm volatile("mapa.shared::cluster.u32 %0, %1, %2;" : "=r"(raddr) : "r"(laddr), "r"(dst_rank));
    asm volatile("mbarrier.arrive.shared::cluster.b64 _, [%0];" :: "r"(raddr) : "memory");
}
__device__ __forceinline__ void mbar_wait_parity(uint32_t addr, uint32_t ph) {
    asm volatile(
        "{\n\t.reg .pred P1;\n"
        "WL_%=:\n\t"
        "mbarrier.try_wait.parity.acquire.cluster.shared::cta.b64 P1, [%0], %1, 0x989680;\n\t"
        "@P1 bra WD_%=;\n\t"
        "bra WL_%=;\n"
        "WD_%=:\n\t}"
        :: "r"(addr), "r"(ph) : "memory");
}
__device__ __forceinline__ void cluster_barrier() {
    asm volatile("barrier.cluster.arrive.aligned;" ::: "memory");
    asm volatile("barrier.cluster.wait.aligned;" ::: "memory");
}

__global__ __launch_bounds__(NTH, 2) __cluster_dims__(CLU, 1, 1)
void umps_mb2_kernel(const float* __restrict__ x,      // (256, 512, 33)
                     const float* __restrict__ core,   // (64, 33, 64)
                     const float* __restrict__ alpha,  // (64)
                     const float* __restrict__ outc,   // (64, 32)
                     float*       __restrict__ out)    // (256, 32)
{
    __shared__ u64   sU[ISL * 128];      // [iL*128 + (f-1)*4 + bp]  8192 B (warp-private rows)
    __shared__ u64   sP[256 * 9];        // [sc*9 + g] swizzled     18432 B
    __shared__ u64   sVu[40];            // [iL*5 + bp]               320 B (this CTA's 8 rows)
    __shared__ u64   sMail[2 * CLU * 32];// [(buf*8+src)*32+pos]     4096 B
    __shared__ float sX[2 * NFX * NBC];  // [buf][f-1][8 b]          2048 B
    __shared__ u64   sBar[2];            // fwd mbarriers (per buf)

    const int tid  = threadIdx.x;
    const int rank = blockIdx.x & 7;
    const int b0   = (blockIdx.x >> 3) * NBC;   // cluster batch base
    const int g    = tid >> 5;                  // warp = local i-row 0..7
    const int l    = tid & 31;                  // lane = j-pair index (j = 2l, 2l+1)
    const uint32_t sx_base   = (uint32_t)__cvta_generic_to_shared(&sX[0]);
    const uint32_t mail_base = (uint32_t)__cvta_generic_to_shared(&sMail[0]);
    const uint32_t bar_base  = (uint32_t)__cvta_generic_to_shared(&sBar[0]);

    // ---- core slice (f=1..32) -> REGISTERS: cR[f-1] = core[rank*8+g][f][2l..2l+1] ----
    float2 cR[NFX];
    {
        const float* cg = core + ((size_t)(rank * ISL + g) * 33) * BOND + 2 * l;
        #pragma unroll
        for (int f = 0; f < NFX; ++f) cR[f] = *(const float2*)(cg + (f + 1) * BOND);
    }

    // ---- init this CTA's V rows: V[iL][b] = alpha[rank*8 + iL] ----
    if (tid < 32) sVu[(tid >> 2) * 5 + (tid & 3)] = pack2(alpha[rank * ISL + (tid >> 2)]);

    // ---- init mbarriers: 8 arrives per completion (one per source rank) ----
    if (tid == 0) {
        asm volatile("mbarrier.init.shared.b64 [%0], %1;" :: "r"(bar_base), "r"(CLU) : "memory");
        asm volatile("mbarrier.init.shared.b64 [%0], %1;" :: "r"(bar_base + 8), "r"(CLU) : "memory");
    }

    // ---- preload X(t=0): exactly one cp.async per thread (f=1..32, 8 b) ----
    {
        int f = tid >> 3, bl = tid & 7;
        cp_async4(sx_base + (uint32_t)(tid * 4),
                  x + ((size_t)(b0 + bl) * TLEN + 0) * 33 + (f + 1));
    }
    cp_async_commit();

    cluster_barrier();   // mbarrier init visible cluster-wide before any remote arrive

    for (int t = 0; t < TLEN; ++t) {
        cp_async_wait0();
        __syncthreads();                          // B0: X(t) landed, sVu(t) visible

        const int buf = t & 1;

        // ---- prefetch X(t+1) into buf^1 ----
        if (t + 1 < TLEN) {
            int f = tid >> 3, bl = tid & 7;
            cp_async4(sx_base + (uint32_t)(((buf ^ 1) * NFX * NBC + tid) * 4),
                      x + ((size_t)(b0 + bl) * TLEN + (t + 1)) * 33 + (f + 1));
        }
        cp_async_commit();

        // ---- U-build (warp-private row g): U[g][f'][bp] = V[g][bp] * X[f'][bp] ----
        {
            const u64* sXu = (const u64*)(sX + buf * (NFX * NBC));
            u64 vb0 = sVu[g * 5 + 0], vb1 = sVu[g * 5 + 1];
            u64 vb2 = sVu[g * 5 + 2], vb3 = sVu[g * 5 + 3];
            u64* Uw = sU + g * 128;
            #pragma unroll
            for (int k = 0; k < 4; ++k) {
                int r = l + 32 * k;               // r = f'*4 + bp
                u64 vv = (r & 2) ? ((r & 1) ? vb3 : vb2) : ((r & 1) ? vb1 : vb0);
                Uw[r] = mul2(vv, sXu[r]);
            }
            __syncwarp();
        }

        // ---- GEMM over f=1..32: acc[jj*4+bp], j = 2l+jj ----
        u64 acc[8];
        #pragma unroll
        for (int q = 0; q < 8; ++q) acc[q] = 0ull;

        const ulonglong2* Ur = (const ulonglong2*)(sU + g * 128);
        #pragma unroll
        for (int f = 0; f < NFX; ++f) {
            ulonglong2 ua = Ur[2 * f];            // bp 0,1 (warp-broadcast)
            ulonglong2 ub = Ur[2 * f + 1];        // bp 2,3
            u64 c0 = pack2(cR[f].x);
            u64 c1 = pack2(cR[f].y);
            fma2(acc[0], ua.x, c0); fma2(acc[1], ua.y, c0);
            fma2(acc[2], ub.x, c0); fma2(acc[3], ub.y, c0);
            fma2(acc[4], ua.x, c1); fma2(acc[5], ua.y, c1);
            fma2(acc[6], ub.x, c1); fma2(acc[7], ub.y, c1);
        }

        // ---- store partials, conflict-free swizzle sc = q*32 + l ----
        #pragma unroll
        for (int q = 0; q < 8; ++q)
            sP[(q * 32 + l) * 9 + g] = acc[q];
        __syncthreads();                          // B2: partials visible

        // ---- reduce 8 i-rows; scatter to owner rank's mailbox ----
        {
            u64 s = sP[tid * 9];
            #pragma unroll
            for (int gg = 1; gg < ISL; ++gg) add2(s, sP[tid * 9 + gg]);
            int jp = tid & 31, q = tid >> 5;
            int jj = q >> 2, bp = q & 3;
            int j  = 2 * jp + jj;
            int own = j >> 3;
            int pos = (j & 7) * 4 + bp;
            st_cluster_u64(mail_base + (uint32_t)(((buf * CLU + rank) * 32 + pos) * 8), own, s);
        }
        __syncthreads();                          // B3: all scatter stores issued

        // ---- signal: thread k arrives on owner k's bar[buf] (cumulative release) ----
        if (tid < CLU) {
            asm volatile("fence.acq_rel.cluster;" ::: "memory");
            mbar_arrive_remote(bar_base + (uint32_t)(buf * 8), tid);
        }

        // ---- consumers wait for all 8 rank-arrives, then build new V ----
        if (tid < 32) {
            mbar_wait_parity(bar_base + (uint32_t)(buf * 8), (uint32_t)((t >> 1) & 1));
            const u64* mb = sMail + buf * (CLU * 32);
            u64 v = mb[tid];
            #pragma unroll
            for (int r = 1; r < CLU; ++r) add2(v, mb[r * 32 + tid]);
            add2(v, sVu[(tid >> 2) * 5 + (tid & 3)]);   // f=0 identity: V_new += V_old
            sVu[(tid >> 2) * 5 + (tid & 3)] = v;
        }
        // sVu visibility for next step via loop-top B0
    }

    // ---- gather final V rows to rank 0 ----
    __syncthreads();
    if (tid < 32) {
        u64 v = sVu[(tid >> 2) * 5 + (tid & 3)];
        st_cluster_u64(mail_base + (uint32_t)((rank * 32 + tid) * 8), 0, v);
    }
    cluster_barrier();

    // ---- epilogue on rank 0: out[b][o] = sum_i V[i][b] * outc[i][o] ----
    if (rank == 0) {
        const float* Vf = (const float*)sMail;   // u64 slot (i>>3)*32 + (i&7)*4 + (b>>1)
        int b = tid >> 5, o = tid & 31;
        float s = 0.f;
        #pragma unroll 8
        for (int i = 0; i < BOND; ++i) {
            float v = Vf[(((i >> 3) * 32 + (i & 7) * 4 + (b >> 1)) << 1) + (b & 1)];
            s = fmaf(v, __ldg(outc + i * OUTD + o), s);
        }
        out[(size_t)(b0 + b) * OUTD + o] = s;
    }
}

extern "C" void kernel_launch(void* const* d_in, const int* in_sizes, int n_in,
                              void* d_out, int out_size) {
    const float* x     = (const float*)d_in[0];   // (256,512,33) fp32
    const float* core  = (const float*)d_in[1];   // (64,33,64)  fp32
    const float* alpha = (const float*)d_in[2];   // (64)        fp32
    const float* outc  = (const float*)d_in[3];   // (64,32)     fp32
    float* out = (float*)d_out;                   // (256,32)    fp32

    // 32 clusters x 8 CTAs = 256 CTAs, 2 CTAs/SM (smem ~33 KB, regs ~112)
    umps_mb2_kernel<<<256, NTH>>>(x, core, alpha, outc, out);
}